// round 1
// baseline (speedup 1.0000x reference)
#include <cuda_runtime.h>
#include <cstdint>

#define DEVINL __device__ __forceinline__

// 4 MB scratch for t = x @ w1^T  (TOKENS x LOWRANK)
__device__ float g_t[4096 * 256];

DEVINL uint32_t smem_u32(const void* p) {
    return (uint32_t)__cvta_generic_to_shared(p);
}

DEVINL void ldsm_x4(uint32_t addr, uint32_t& r0, uint32_t& r1, uint32_t& r2, uint32_t& r3) {
    asm volatile("ldmatrix.sync.aligned.m8n8.x4.shared.b16 {%0,%1,%2,%3}, [%4];"
                 : "=r"(r0), "=r"(r1), "=r"(r2), "=r"(r3)
                 : "r"(addr));
}

DEVINL uint32_t f2tf32(uint32_t x) {
    uint32_t y;
    asm volatile("cvt.rna.tf32.f32 %0, %1;" : "=r"(y) : "f"(__uint_as_float(x)));
    return y;
}

DEVINL void mma_tf32(float c[4], uint32_t a0, uint32_t a1, uint32_t a2, uint32_t a3,
                     uint32_t b0, uint32_t b1) {
    asm volatile(
        "mma.sync.aligned.m16n8k8.row.col.f32.tf32.tf32.f32 "
        "{%0,%1,%2,%3}, {%4,%5,%6,%7}, {%8,%9}, {%0,%1,%2,%3};"
        : "+f"(c[0]), "+f"(c[1]), "+f"(c[2]), "+f"(c[3])
        : "r"(a0), "r"(a1), "r"(a2), "r"(a3), "r"(b0), "r"(b1));
}

DEVINL void cp16(uint32_t saddr, const void* g) {
    asm volatile("cp.async.ca.shared.global [%0], [%1], 16;" :: "r"(saddr), "l"(g));
}
DEVINL void cp_commit() { asm volatile("cp.async.commit_group;"); }
template <int N>
DEVINL void cp_wait() { asm volatile("cp.async.wait_group %0;" :: "n"(N)); }

// Segmented NT GEMM: C[m, n] = (bias) + sum_seg sum_k A_seg[m,k] * B_seg[n,k]
// A row-major [M x K_seg] (per-seg lda), B row-major [N_seg x K_seg] (per-seg ldb).
// MODE 0: t = x @ w1^T  (1 segment, K=4096), C = g_t (ldc 256)
// MODE 1: out = b + t @ w2_ob^T + sum_a x_blk @ W_f^T  (6 segments, K=256 each), ldc 4096
template <int BM, int BN, int WARPS_M, int WARPS_N, int NSEG, int KPS, int MODE>
__global__ void __launch_bounds__(WARPS_M * WARPS_N * 32)
gemm_tf32_seg(const float* __restrict__ x,
              const float* __restrict__ weight,
              const float* __restrict__ w1,
              const float* __restrict__ w2,
              const float* __restrict__ bias,
              const int* __restrict__ flat,
              float* __restrict__ out) {
    constexpr int THREADS = WARPS_M * WARPS_N * 32;
    constexpr int SROW = 20;              // floats per shared row (16 data + 4 pad)
    constexpr int MT = (BM / WARPS_M) / 16;
    constexpr int NT = (BN / WARPS_N) / 8;
    constexpr int KT = NSEG * KPS;

    __shared__ float sA[2][BM * SROW];
    __shared__ float sB[2][BN * SROW];
    __shared__ const float* sAp[NSEG];
    __shared__ const float* sBp[NSEG];
    __shared__ int sLda[NSEG];
    __shared__ int sLdb[NSEG];

    const int tid = threadIdx.x;
    const int m0 = blockIdx.x * BM;
    const int nb0 = blockIdx.y * BN;   // segment-local column block

    if (tid == 0) {
        if (MODE == 0) {
            sAp[0] = x;  sLda[0] = 4096;
            sBp[0] = w1; sLdb[0] = 4096;
        } else {
            const int ob = blockIdx.z;
            sAp[0] = g_t;              sLda[0] = 256;
            sBp[0] = w2 + ob * 65536;  sLdb[0] = 256;
#pragma unroll
            for (int a = 0; a < 5; ++a) {
                int f = flat[ob * 5 + a];
                sAp[1 + a] = x + (f / 5) * 256;      sLda[1 + a] = 4096;
                sBp[1 + a] = weight + f * 65536;     sLdb[1 + a] = 256;
            }
        }
    }
    __syncthreads();

    const int lane = tid & 31;
    const int warp = tid >> 5;
    const int wm0 = (warp % WARPS_M) * (BM / WARPS_M);
    const int wn0 = (warp / WARPS_M) * (BN / WARPS_N);

    // ldmatrix per-lane offsets (A fragment and B fragment layouts)
    const int lrA = (lane & 7) + ((lane >> 3) & 1) * 8;   // row within 16
    const int lcA = ((lane >> 3) & 2) * 2;                 // col 0 or 4
    const int brB = (lane & 7) + ((lane >> 3) & 2) * 4;   // row within 16
    const int bcB = ((lane >> 3) & 1) * 4;                 // col 0 or 4

    float acc[MT][NT][4] = {};

    auto load_tile = [&](int kt, int buf) {
        const int seg = kt / KPS;
        const int koff = (kt - seg * KPS) * 16;
        const float* Ab = sAp[seg];
        const float* Bb = sBp[seg];
        const int lda = sLda[seg];
        const int ldb = sLdb[seg];
        constexpr int TOTAL = (BM + BN) * 4;
#pragma unroll
        for (int c = 0; c < TOTAL / THREADS; ++c) {
            int idx = tid + c * THREADS;
            if (idx < BM * 4) {
                int r = idx >> 2, ch = idx & 3;
                cp16(smem_u32(&sA[buf][r * SROW + ch * 4]),
                     Ab + (size_t)(m0 + r) * lda + koff + ch * 4);
            } else {
                int j = idx - BM * 4;
                int r = j >> 2, ch = j & 3;
                cp16(smem_u32(&sB[buf][r * SROW + ch * 4]),
                     Bb + (size_t)(nb0 + r) * ldb + koff + ch * 4);
            }
        }
    };

    auto compute = [&](int buf) {
        const float* Abase = sA[buf];
        const float* Bbase = sB[buf];
#pragma unroll
        for (int kk = 0; kk < 2; ++kk) {
            uint32_t a[MT][4];
#pragma unroll
            for (int mt = 0; mt < MT; ++mt) {
                uint32_t addr = smem_u32(Abase + (wm0 + mt * 16 + lrA) * SROW + kk * 8 + lcA);
                ldsm_x4(addr, a[mt][0], a[mt][1], a[mt][2], a[mt][3]);
#pragma unroll
                for (int r = 0; r < 4; ++r) a[mt][r] = f2tf32(a[mt][r]);
            }
            uint32_t b[NT][2];
#pragma unroll
            for (int p = 0; p < NT / 2; ++p) {
                uint32_t addr = smem_u32(Bbase + (wn0 + p * 16 + brB) * SROW + kk * 8 + bcB);
                uint32_t r0, r1, r2, r3;
                ldsm_x4(addr, r0, r1, r2, r3);
                b[2 * p][0] = f2tf32(r0);
                b[2 * p][1] = f2tf32(r1);
                b[2 * p + 1][0] = f2tf32(r2);
                b[2 * p + 1][1] = f2tf32(r3);
            }
#pragma unroll
            for (int mt = 0; mt < MT; ++mt)
#pragma unroll
                for (int nt = 0; nt < NT; ++nt)
                    mma_tf32(acc[mt][nt], a[mt][0], a[mt][1], a[mt][2], a[mt][3],
                             b[nt][0], b[nt][1]);
        }
    };

    load_tile(0, 0);
    cp_commit();

#pragma unroll 1
    for (int kt = 0; kt < KT; ++kt) {
        const int buf = kt & 1;
        if (kt + 1 < KT) {
            load_tile(kt + 1, buf ^ 1);
            cp_commit();
            cp_wait<1>();
        } else {
            cp_wait<0>();
        }
        __syncthreads();
        compute(buf);
        __syncthreads();
    }

    // Epilogue
    float* Cp = (MODE == 0) ? g_t : out;
    const int ldc = (MODE == 0) ? 256 : 4096;
    const int n0g = (MODE == 1 ? (int)blockIdx.z * 256 : 0) + nb0;

#pragma unroll
    for (int mt = 0; mt < MT; ++mt) {
        const int row = m0 + wm0 + mt * 16 + (lane >> 2);
#pragma unroll
        for (int nt = 0; nt < NT; ++nt) {
            const int col = n0g + wn0 + nt * 8 + (lane & 3) * 2;
            float b0 = 0.f, b1 = 0.f;
            if (MODE == 1) { b0 = __ldg(&bias[col]); b1 = __ldg(&bias[col + 1]); }
            float2 v0 = make_float2(acc[mt][nt][0] + b0, acc[mt][nt][1] + b1);
            float2 v1 = make_float2(acc[mt][nt][2] + b0, acc[mt][nt][3] + b1);
            *reinterpret_cast<float2*>(&Cp[(size_t)row * ldc + col]) = v0;
            *reinterpret_cast<float2*>(&Cp[(size_t)(row + 8) * ldc + col]) = v1;
        }
    }
}

extern "C" void kernel_launch(void* const* d_in, const int* in_sizes, int n_in,
                              void* d_out, int out_size) {
    (void)in_sizes; (void)n_in; (void)out_size;
    const float* x      = (const float*)d_in[0];
    const float* weight = (const float*)d_in[1];
    const float* w1     = (const float*)d_in[2];
    const float* w2     = (const float*)d_in[3];
    const float* bias   = (const float*)d_in[4];
    const int*   flat   = (const int*)d_in[5];
    float* out = (float*)d_out;

    // Kernel A: t = x @ w1^T   (M=4096, N=256, K=4096)
    // BM=64, BN=128, warps 2x2 (128 threads), grid 64 x 2
    gemm_tf32_seg<64, 128, 2, 2, 1, 256, 0>
        <<<dim3(64, 2, 1), 128>>>(x, weight, w1, w2, bias, flat, out);

    // Kernel B: out = b + t @ w2_ob^T + butterfly   (per ob: M=4096, N=256, K=6*256)
    // BM=128, BN=128, warps 4x2 (256 threads), grid 32 x 2 x 16
    gemm_tf32_seg<128, 128, 4, 2, 6, 16, 1>
        <<<dim3(32, 2, 16), 256>>>(x, weight, w1, w2, bias, flat, out);
}